// round 8
// baseline (speedup 1.0000x reference)
#include <cuda_runtime.h>
#include <cuda_bf16.h>
#include <cstdint>

#define N0 8000
#define N1 4000
#define N2 2000
#define DIM 128
#define XW 384

// adj bf16 hi/lo planes (prepass)
__device__ __nv_bfloat16 g_Ah0[(size_t)N0 * N0];
__device__ __nv_bfloat16 g_Al0[(size_t)N0 * N0];
__device__ __nv_bfloat16 g_Ah1[(size_t)N1 * N1];
__device__ __nv_bfloat16 g_Al1[(size_t)N1 * N1];
__device__ __nv_bfloat16 g_Ah2[(size_t)N2 * N2];
__device__ __nv_bfloat16 g_Al2[(size_t)N2 * N2];
// Xt = X^T [384][N_i], bf16 hi/lo planes
__device__ __nv_bfloat16 g_Bh0[XW * N0];
__device__ __nv_bfloat16 g_Bl0[XW * N0];
__device__ __nv_bfloat16 g_Bh1[XW * N1];
__device__ __nv_bfloat16 g_Bl1[XW * N1];
__device__ __nv_bfloat16 g_Bh2[XW * N2];
__device__ __nv_bfloat16 g_Bl2[XW * N2];
// fp32 Y partials (level 0 K-split x2)
__device__ float g_Y0[N0 * XW];
__device__ float g_Y0b[N0 * XW];
__device__ float g_Y1[N1 * XW];
__device__ float g_Y2[N2 * XW];

// ===========================================================================
// helpers
// ===========================================================================
__device__ __forceinline__ uint32_t smem_to_u32(const void* p) {
    uint32_t a;
    asm("{ .reg .u64 t; cvta.to.shared.u64 t, %1; cvt.u32.u64 %0, t; }" : "=r"(a) : "l"(p));
    return a;
}
__device__ __forceinline__ void ldsm4(uint32_t* r, uint32_t addr) {
    asm volatile("ldmatrix.sync.aligned.m8n8.x4.shared.b16 {%0,%1,%2,%3}, [%4];"
                 : "=r"(r[0]), "=r"(r[1]), "=r"(r[2]), "=r"(r[3]) : "r"(addr));
}
__device__ __forceinline__ void mma16816(float* c, const uint32_t* a, const uint32_t* b) {
    asm volatile(
        "mma.sync.aligned.m16n8k16.row.col.f32.bf16.bf16.f32 "
        "{%0,%1,%2,%3}, {%4,%5,%6,%7}, {%8,%9}, {%0,%1,%2,%3};"
        : "+f"(c[0]), "+f"(c[1]), "+f"(c[2]), "+f"(c[3])
        : "r"(a[0]), "r"(a[1]), "r"(a[2]), "r"(a[3]), "r"(b[0]), "r"(b[1]));
}
__device__ __forceinline__ void cpa16(uint32_t d, const void* s, int sz) {
    asm volatile("cp.async.cg.shared.global [%0], [%1], 16, %2;"
                 :: "r"(d), "l"(s), "r"(sz) : "memory");
}
#define CP_COMMIT() asm volatile("cp.async.commit_group;" ::: "memory")
#define CP_WAIT2() asm volatile("cp.async.wait_group 2;" ::: "memory")

__device__ __forceinline__ uint32_t pkbits(__nv_bfloat16 x, __nv_bfloat16 y) {
    __nv_bfloat162 t;
    t.x = x; t.y = y;
    return reinterpret_cast<uint32_t&>(t);
}
__device__ __forceinline__ void split2(float a, float b, uint32_t& hi, uint32_t& lo) {
    __nv_bfloat16 xa = __float2bfloat16_rn(a), xb = __float2bfloat16_rn(b);
    hi = pkbits(xa, xb);
    lo = pkbits(__float2bfloat16_rn(a - __bfloat162float(xa)),
                __float2bfloat16_rn(b - __bfloat162float(xb)));
}

// ===========================================================================
// Prepass: all three adj -> bf16 hi/lo planes, one launch
// ===========================================================================
__device__ __forceinline__ void cvt_range(const float4* __restrict__ in,
                                          uint2* __restrict__ hi, uint2* __restrict__ lo,
                                          int n4, int start, int stride) {
    for (int i = start; i < n4; i += stride) {
        float4 v = in[i];
        uint2 h, l;
        split2(v.x, v.y, h.x, l.x);
        split2(v.z, v.w, h.y, l.y);
        hi[i] = h;
        lo[i] = l;
    }
}

__global__ void k_cvt_all(const float4* a0, uint2* h0, uint2* l0,
                          const float4* a1, uint2* h1, uint2* l1,
                          const float4* a2, uint2* h2, uint2* l2) {
    int start = blockIdx.x * blockDim.x + threadIdx.x;
    int stride = gridDim.x * blockDim.x;
    cvt_range(a0, h0, l0, 16000000, start, stride);
    cvt_range(a1, h1, l1, 4000000, start, stride);
    cvt_range(a2, h2, l2, 1000000, start, stride);
}

// ===========================================================================
// Fused zero of scatter-target B regions
// ===========================================================================
__global__ void k_zero_all(float4* __restrict__ a0, float4* __restrict__ a1,
                           float4* __restrict__ a2, float4* __restrict__ a3) {
    int i = blockIdx.x * blockDim.x + threadIdx.x;
    int st = gridDim.x * blockDim.x;
    float4 z = make_float4(0.f, 0.f, 0.f, 0.f);
    for (int k = i; k < 256000; k += st) a0[k] = z;
    for (int k = i; k < 256000; k += st) a1[k] = z;
    for (int k = i; k < 64000; k += st) a2[k] = z;
    for (int k = i; k < 64000; k += st) a3[k] = z;
}

// ===========================================================================
// Fused transposed placement: Xt[rowOff+f][r] = H[chain(r)][f] (bf16 hi/lo)
// ===========================================================================
__device__ __forceinline__ void trans_blk(float (*tile)[33],
                                          __nv_bfloat16* __restrict__ Bh,
                                          __nv_bfloat16* __restrict__ Bl, int ld,
                                          const float* __restrict__ H, int rows,
                                          const int* __restrict__ s1,
                                          const int* __restrict__ s2, int rowOff, int blk) {
    int tid = threadIdx.x;
    int r0 = blk * 32;
#pragma unroll
    for (int t = 0; t < 4; t++) {
        int g = tid + t * 256;
        int r = g >> 5;
        int c4 = g & 31;
        int sr = r0 + r;
        float4 v = make_float4(0.f, 0.f, 0.f, 0.f);
        if (sr < rows) {
            int s = sr;
            if (s2) s = s2[s];
            if (s1) s = s1[s];
            v = *reinterpret_cast<const float4*>(H + (size_t)s * DIM + c4 * 4);
        }
        tile[c4 * 4 + 0][r] = v.x;
        tile[c4 * 4 + 1][r] = v.y;
        tile[c4 * 4 + 2][r] = v.z;
        tile[c4 * 4 + 3][r] = v.w;
    }
    __syncthreads();
    int f = tid >> 1;
    int half = tid & 1;
#pragma unroll
    for (int m4 = 0; m4 < 4; m4++) {
        int lc = half * 16 + m4 * 4;
        int col = r0 + lc;
        if (col < rows) {
            uint2 h, l;
            split2(tile[f][lc], tile[f][lc + 1], h.x, l.x);
            split2(tile[f][lc + 2], tile[f][lc + 3], h.y, l.y);
            size_t off = (size_t)(rowOff + f) * ld + col;
            *reinterpret_cast<uint2*>(Bh + off) = h;
            *reinterpret_cast<uint2*>(Bl + off) = l;
        }
    }
}

__global__ __launch_bounds__(256) void k_trans_all(
    __nv_bfloat16* Bh0p, __nv_bfloat16* Bl0p, __nv_bfloat16* Bh1p, __nv_bfloat16* Bl1p,
    __nv_bfloat16* Bh2p, __nv_bfloat16* Bl2p,
    const float* h0, const float* h1, const float* h2,
    const int* idx0, const int* idx1) {
    __shared__ float tile[128][33];
    int b = blockIdx.x;
    if (b < 250)      trans_blk(tile, Bh0p, Bl0p, N0, h0, N0, nullptr, nullptr, 0, b);
    else if (b < 375) trans_blk(tile, Bh1p, Bl1p, N1, h0, N1, idx0, nullptr, 0, b - 250);
    else if (b < 500) trans_blk(tile, Bh1p, Bl1p, N1, h1, N1, nullptr, nullptr, 128, b - 375);
    else if (b < 563) trans_blk(tile, Bh2p, Bl2p, N2, h0, N2, idx0, idx1, 0, b - 500);
    else if (b < 626) trans_blk(tile, Bh2p, Bl2p, N2, h1, N2, idx1, nullptr, 128, b - 563);
    else              trans_blk(tile, Bh2p, Bl2p, N2, h2, N2, nullptr, nullptr, 256, b - 626);
}

// ===========================================================================
// Fused scattered placement (up path)
// ===========================================================================
__device__ __forceinline__ void scat_row(__nv_bfloat16* __restrict__ Bh,
                                         __nv_bfloat16* __restrict__ Bl, int ld,
                                         const float* __restrict__ H,
                                         const int* __restrict__ d1,
                                         const int* __restrict__ d2, int rowOff,
                                         int r, int f) {
    float v = H[(size_t)r * DIM + f];
    int dr = r;
    if (d2) dr = d2[dr];
    if (d1) dr = d1[dr];
    __nv_bfloat16 h = __float2bfloat16_rn(v);
    size_t off = (size_t)(rowOff + f) * ld + dr;
    Bh[off] = h;
    Bl[off] = __float2bfloat16_rn(v - __bfloat162float(h));
}

__global__ __launch_bounds__(256) void k_scatter_all(
    __nv_bfloat16* Bh0p, __nv_bfloat16* Bl0p, __nv_bfloat16* Bh1p, __nv_bfloat16* Bl1p,
    const float* h1, const float* h2, const int* idx0, const int* idx1) {
    int b = blockIdx.x;
    int f = threadIdx.x & 127;
    int rh = threadIdx.x >> 7;
    if (b < 2000)      scat_row(Bh0p, Bl0p, N0, h1, idx0, nullptr, 128, b * 2 + rh, f);
    else if (b < 3000) scat_row(Bh0p, Bl0p, N0, h2, idx0, idx1, 256, (b - 2000) * 2 + rh, f);
    else               scat_row(Bh1p, Bl1p, N1, h2, idx1, nullptr, 256, (b - 3000) * 2 + rh, f);
}

// ===========================================================================
// bf16-split mma.sync GEMM — all-ldmatrix mainloop (R6 body), balanced grid.
// CTA tile M=64, N=128. 4 stages x 24KB. 1035 CTAs, level-0 K-split x2.
// ===========================================================================
#define OFF_AH 0
#define OFF_AL 4096
#define OFF_BH 8192
#define OFF_BL 16384
#define STAGE_BYTES 24576
#define SMEM_MMA (4 * STAGE_BYTES)   // 98304

__device__ __forceinline__ void issue_stage(
    uint32_t stg, const __nv_bfloat16* __restrict__ Ah, const __nv_bfloat16* __restrict__ Al,
    const __nv_bfloat16* __restrict__ Bh, const __nv_bfloat16* __restrict__ Bl,
    int rowBase, int nBase, int M, int ld, int gk0, int Klim, int tid) {
    // A hi/lo: 64 rows x 4 chunks of 16B
    {
        int row = tid >> 2, c = tid & 3;
        int gk = gk0 + c * 8;
        size_t so = (size_t)(rowBase + row) * ld + gk;
        uint32_t d = stg + row * 64 + ((c ^ ((row >> 1) & 3)) << 4);
        int p = (rowBase + row < M && gk < Klim) ? 16 : 0;
        cpa16(d + OFF_AH, Ah + so, p);
        cpa16(d + OFF_AL, Al + so, p);
    }
    // B hi/lo: 128 rows x 4 chunks
#pragma unroll
    for (int i = 0; i < 2; i++) {
        int t = tid + i * 256;
        int row = t >> 2, c = t & 3;
        int gk = gk0 + c * 8;
        size_t so = (size_t)(nBase + row) * ld + gk;
        uint32_t d = stg + row * 64 + ((c ^ ((row >> 1) & 3)) << 4);
        int p = (gk < Klim) ? 16 : 0;
        cpa16(d + OFF_BH, Bh + so, p);
        cpa16(d + OFF_BL, Bl + so, p);
    }
}

__global__ __launch_bounds__(256, 2)
void k_mma(const __nv_bfloat16* __restrict__ Ah0p, const __nv_bfloat16* __restrict__ Al0p,
           const __nv_bfloat16* __restrict__ Ah1p, const __nv_bfloat16* __restrict__ Al1p,
           const __nv_bfloat16* __restrict__ Ah2p, const __nv_bfloat16* __restrict__ Al2p,
           const __nv_bfloat16* __restrict__ Bh0p, const __nv_bfloat16* __restrict__ Bl0p,
           const __nv_bfloat16* __restrict__ Bh1p, const __nv_bfloat16* __restrict__ Bl1p,
           const __nv_bfloat16* __restrict__ Bh2p, const __nv_bfloat16* __restrict__ Bl2p,
           float* __restrict__ Y0, float* __restrict__ Y0b,
           float* __restrict__ Y1, float* __restrict__ Y2) {
    extern __shared__ char sm[];
    int tid = threadIdx.x;
    int lane = tid & 31;
    int wid = tid >> 5;
    int bx = blockIdx.x;

    const __nv_bfloat16 *Ah, *Al, *Bh, *Bl;
    float* Y;
    int M, ld, mt, nt, kOff, nIter, Klim;
    if (bx < 750) {
        mt = bx / 6;
        int r = bx % 6;
        nt = r >> 1;
        int ks = r & 1;
        Ah = Ah0p; Al = Al0p; Bh = Bh0p; Bl = Bl0p; Y = ks ? Y0b : Y0;
        M = N0; ld = N0; kOff = ks * 4000; nIter = 125; Klim = N0;
    } else if (bx < 939) {
        int t = bx - 750;
        mt = t / 3; nt = t % 3;
        Ah = Ah1p; Al = Al1p; Bh = Bh1p; Bl = Bl1p; Y = Y1;
        M = N1; ld = N1; kOff = 0; nIter = 125; Klim = N1;
    } else {
        int t = bx - 939;
        mt = t / 3; nt = t % 3;
        Ah = Ah2p; Al = Al2p; Bh = Bh2p; Bl = Bl2p; Y = Y2;
        M = N2; ld = N2; kOff = 0; nIter = 63; Klim = N2;
    }
    int rowBase = mt * 64;
    int nBase = nt * 128;

    uint32_t sbase = smem_to_u32(sm);
    int wm = wid & 1;    // 2 m-warps x 32 rows
    int wn = wid >> 1;   // 4 n-warps x 32 cols

    // ldmatrix geometry
    int rA = lane & 15;
    int cA = lane >> 4;
    int rBl = (lane & 7) + ((lane >> 4) & 1) * 8;
    int cB = (lane >> 3) & 1;
    uint32_t arow[2], aswz[2], brow[2], bswz[2];
#pragma unroll
    for (int mi = 0; mi < 2; mi++) {
        int r = wm * 32 + mi * 16 + rA;
        arow[mi] = (uint32_t)r * 64;
        aswz[mi] = (r >> 1) & 3;
    }
#pragma unroll
    for (int nb = 0; nb < 2; nb++) {
        int r = wn * 32 + nb * 16 + rBl;
        brow[nb] = (uint32_t)r * 64;
        bswz[nb] = (r >> 1) & 3;
    }

    float acc[2][4][4];
#pragma unroll
    for (int mi = 0; mi < 2; mi++)
#pragma unroll
        for (int ni = 0; ni < 4; ni++)
#pragma unroll
            for (int c = 0; c < 4; c++) acc[mi][ni][c] = 0.f;

#pragma unroll
    for (int s = 0; s < 3; s++) {
        issue_stage(sbase + s * STAGE_BYTES, Ah, Al, Bh, Bl, rowBase, nBase, M, ld,
                    kOff + s * 32, Klim, tid);
        CP_COMMIT();
    }

    for (int it = 0; it < nIter; it++) {
        CP_WAIT2();
        __syncthreads();
        if (it + 3 < nIter)
            issue_stage(sbase + ((it + 3) & 3) * STAGE_BYTES, Ah, Al, Bh, Bl,
                        rowBase, nBase, M, ld, kOff + (it + 3) * 32, Klim, tid);
        CP_COMMIT();

        uint32_t stg = sbase + (it & 3) * STAGE_BYTES;
#pragma unroll
        for (int k16 = 0; k16 < 2; k16++) {
            uint32_t ah[2][4], al[2][4], bh[2][4], bl[2][4];
#pragma unroll
            for (int mi = 0; mi < 2; mi++) {
                uint32_t off = arow[mi] + ((((uint32_t)(k16 * 2 + cA)) ^ aswz[mi]) << 4);
                ldsm4(ah[mi], stg + OFF_AH + off);
                ldsm4(al[mi], stg + OFF_AL + off);
            }
#pragma unroll
            for (int nb = 0; nb < 2; nb++) {
                uint32_t off = brow[nb] + ((((uint32_t)(k16 * 2 + cB)) ^ bswz[nb]) << 4);
                ldsm4(bh[nb], stg + OFF_BH + off);
                ldsm4(bl[nb], stg + OFF_BL + off);
            }
#pragma unroll
            for (int mi = 0; mi < 2; mi++)
#pragma unroll
                for (int nb = 0; nb < 2; nb++) {
                    mma16816(acc[mi][2 * nb], ah[mi], &bh[nb][0]);
                    mma16816(acc[mi][2 * nb + 1], ah[mi], &bh[nb][2]);
                    mma16816(acc[mi][2 * nb], al[mi], &bh[nb][0]);
                    mma16816(acc[mi][2 * nb + 1], al[mi], &bh[nb][2]);
                    mma16816(acc[mi][2 * nb], ah[mi], &bl[nb][0]);
                    mma16816(acc[mi][2 * nb + 1], ah[mi], &bl[nb][2]);
                }
        }
    }

    int colB = nBase + wn * 32 + (lane & 3) * 2;
#pragma unroll
    for (int mi = 0; mi < 2; mi++)
#pragma unroll
        for (int h = 0; h < 2; h++) {
            int row = rowBase + wm * 32 + mi * 16 + (lane >> 2) + h * 8;
            if (row < M) {
                float* yp = Y + (size_t)row * XW + colB;
#pragma unroll
                for (int ni = 0; ni < 4; ni++)
                    *reinterpret_cast<float2*>(yp + ni * 8) =
                        make_float2(acc[mi][ni][2 * h], acc[mi][ni][2 * h + 1]);
            }
        }
}

// ===========================================================================
// Fused fp32 epilogue; level-0 sums Y0 + Y0b partials.
// ===========================================================================
__global__ __launch_bounds__(256) void k_epi(const float* __restrict__ Y0a,
                                             const float* __restrict__ Y0bp,
                                             const float* __restrict__ Y1a,
                                             const float* __restrict__ Y2a,
                                             const float* __restrict__ Wall,
                                             const float* __restrict__ ball,
                                             float* __restrict__ outAll) {
    __shared__ float As[16][132];
    __shared__ float Bs[16][128];
    int tid = threadIdx.x;
    int tx = tid & 15;
    int ty = tid >> 4;
    int bx = blockIdx.x;

    const float* Y;
    const float* Yb = nullptr;
    float* out;
    int M, ilev, mt;
    if (bx < 63) {
        Y = Y0a; Yb = Y0bp; out = outAll; M = N0; ilev = 0; mt = bx;
    } else if (bx < 95) {
        Y = Y1a; out = outAll + (size_t)N0 * DIM; M = N1; ilev = 1; mt = bx - 63;
    } else {
        Y = Y2a; out = outAll + (size_t)(N0 + N1) * DIM; M = N2; ilev = 2; mt = bx - 95;
    }
    int rowBase = mt * 128;

    float sum[8][8];
#pragma unroll
    for (int i = 0; i < 8; i++)
#pragma unroll
        for (int j = 0; j < 8; j++) sum[i][j] = 0.f;

    for (int jb = 0; jb < 3; jb++) {
        const float* W = Wall + (size_t)(ilev * 3 + jb) * DIM * DIM;
        float acc[8][8];
#pragma unroll
        for (int i = 0; i < 8; i++)
#pragma unroll
            for (int j = 0; j < 8; j++) acc[i][j] = 0.f;

        for (int k0 = 0; k0 < DIM; k0 += 16) {
#pragma unroll
            for (int l = 0; l < 2; l++) {
                int s = tid + l * 256;
                int r = s >> 2;
                int kq = (s & 3) * 4;
                int grow = rowBase + r;
                float4 v = make_float4(0.f, 0.f, 0.f, 0.f);
                if (grow < M) {
                    size_t off = (size_t)grow * XW + jb * DIM + k0 + kq;
                    v = *reinterpret_cast<const float4*>(Y + off);
                    if (Yb) {
                        float4 w = *reinterpret_cast<const float4*>(Yb + off);
                        v.x += w.x; v.y += w.y; v.z += w.z; v.w += w.w;
                    }
                }
                As[kq + 0][r] = v.x;
                As[kq + 1][r] = v.y;
                As[kq + 2][r] = v.z;
                As[kq + 3][r] = v.w;
            }
#pragma unroll
            for (int l = 0; l < 2; l++) {
                int s = tid + l * 256;
                int kr = s >> 5;
                int c4 = (s & 31) * 4;
                *reinterpret_cast<float4*>(&Bs[kr][c4]) =
                    *reinterpret_cast<const float4*>(W + (size_t)(k0 + kr) * DIM + c4);
            }
            __syncthreads();
#pragma unroll
            for (int kk = 0; kk < 16; kk++) {
                float a[8], b[8];
                *reinterpret_cast<float4*>(a) = *reinterpret_cast<const float4*>(&As[kk][ty * 8]);
                *reinterpret_cast<float4*>(a + 4) = *reinterpret_cast<const float4*>(&As[kk][ty * 8 + 4]);
                *reinterpret_cast<float4*>(b) = *reinterpret_cast<const float4*>(&Bs[kk][tx * 8]);
                *reinterpret_cast<float4*>(b + 4) = *reinterpret_cast<const float4*>(&Bs[kk][tx * 8 + 4]);
#pragma unroll
                for (int i = 0; i < 8; i++)
#pragma unroll
                    for (int j = 0; j < 8; j++) acc[i][j] += a[i] * b[j];
            }
            __syncthreads();
        }
        const float* bvec = ball + (size_t)(ilev * 3 + jb) * DIM;
#pragma unroll
        for (int j = 0; j < 8; j++) {
            float bb = bvec[tx * 8 + j];
#pragma unroll
            for (int i = 0; i < 8; i++) sum[i][j] += fmaxf(acc[i][j] + bb, 0.f);
        }
    }

#pragma unroll
    for (int i = 0; i < 8; i++) {
        int grow = rowBase + ty * 8 + i;
        if (grow < M) {
            float* op = out + (size_t)grow * DIM + tx * 8;
            *reinterpret_cast<float4*>(op) = make_float4(sum[i][0], sum[i][1], sum[i][2], sum[i][3]);
            *reinterpret_cast<float4*>(op + 4) = make_float4(sum[i][4], sum[i][5], sum[i][6], sum[i][7]);
        }
    }
}

// ===========================================================================
extern "C" void kernel_launch(void* const* d_in, const int* in_sizes, int n_in,
                              void* d_out, int out_size) {
    const float* adj0 = (const float*)d_in[0];
    const float* adj1 = (const float*)d_in[1];
    const float* adj2 = (const float*)d_in[2];
    const float* h0 = (const float*)d_in[3];
    const float* h1 = (const float*)d_in[4];
    const float* h2 = (const float*)d_in[5];
    const int* idx0 = (const int*)d_in[6];
    const int* idx1 = (const int*)d_in[7];
    const float* Ws = (const float*)d_in[8];
    const float* bs = (const float*)d_in[9];
    float* out = (float*)d_out;

    __nv_bfloat16 *Ah0, *Al0, *Ah1, *Al1, *Ah2, *Al2;
    __nv_bfloat16 *Bh0, *Bl0, *Bh1, *Bl1, *Bh2, *Bl2;
    float *Y0, *Y0b, *Y1, *Y2;
    cudaGetSymbolAddress((void**)&Ah0, g_Ah0);
    cudaGetSymbolAddress((void**)&Al0, g_Al0);
    cudaGetSymbolAddress((void**)&Ah1, g_Ah1);
    cudaGetSymbolAddress((void**)&Al1, g_Al1);
    cudaGetSymbolAddress((void**)&Ah2, g_Ah2);
    cudaGetSymbolAddress((void**)&Al2, g_Al2);
    cudaGetSymbolAddress((void**)&Bh0, g_Bh0);
    cudaGetSymbolAddress((void**)&Bl0, g_Bl0);
    cudaGetSymbolAddress((void**)&Bh1, g_Bh1);
    cudaGetSymbolAddress((void**)&Bl1, g_Bl1);
    cudaGetSymbolAddress((void**)&Bh2, g_Bh2);
    cudaGetSymbolAddress((void**)&Bl2, g_Bl2);
    cudaGetSymbolAddress((void**)&Y0, g_Y0);
    cudaGetSymbolAddress((void**)&Y0b, g_Y0b);
    cudaGetSymbolAddress((void**)&Y1, g_Y1);
    cudaGetSymbolAddress((void**)&Y2, g_Y2);

    cudaFuncSetAttribute(k_mma, cudaFuncAttributeMaxDynamicSharedMemorySize, SMEM_MMA);

    // 1. adj -> bf16 hi/lo (one fused launch)
    k_cvt_all<<<1184, 256>>>((const float4*)adj0, (uint2*)Ah0, (uint2*)Al0,
                             (const float4*)adj1, (uint2*)Ah1, (uint2*)Al1,
                             (const float4*)adj2, (uint2*)Ah2, (uint2*)Al2);

    // 2. Zero scatter-target B regions
    k_zero_all<<<640, 256>>>((float4*)(Bh0 + (size_t)128 * N0),
                             (float4*)(Bl0 + (size_t)128 * N0),
                             (float4*)(Bh1 + (size_t)256 * N1),
                             (float4*)(Bl1 + (size_t)256 * N1));

    // 3. Build Xt bf16 hi/lo
    k_trans_all<<<689, 256>>>(Bh0, Bl0, Bh1, Bl1, Bh2, Bl2, h0, h1, h2, idx0, idx1);
    k_scatter_all<<<4000, 256>>>(Bh0, Bl0, Bh1, Bl1, h1, h2, idx0, idx1);

    // 4. Y_i = adj_i @ X_i — all-ldmatrix bf16-split tensor GEMM, balanced grid
    k_mma<<<1035, 256, SMEM_MMA>>>(Ah0, Al0, Ah1, Al1, Ah2, Al2,
                                   Bh0, Bl0, Bh1, Bl1, Bh2, Bl2,
                                   Y0, Y0b, Y1, Y2);

    // 5. Fused epilogue
    k_epi<<<111, 256>>>(Y0, Y0b, Y1, Y2, Ws, bs, out);
}

// round 9
// speedup vs baseline: 1.4008x; 1.4008x over previous
#include <cuda_runtime.h>
#include <cuda_bf16.h>
#include <cstdint>

#define N0 8000
#define N1 4000
#define N2 2000
#define DIM 128
#define XW 384

// adj bf16 hi/lo planes (prepass)
__device__ __nv_bfloat16 g_Ah0[(size_t)N0 * N0];
__device__ __nv_bfloat16 g_Al0[(size_t)N0 * N0];
__device__ __nv_bfloat16 g_Ah1[(size_t)N1 * N1];
__device__ __nv_bfloat16 g_Al1[(size_t)N1 * N1];
__device__ __nv_bfloat16 g_Ah2[(size_t)N2 * N2];
__device__ __nv_bfloat16 g_Al2[(size_t)N2 * N2];
// Xt = X^T [384][N_i], bf16 hi/lo planes
__device__ __nv_bfloat16 g_Bh0[XW * N0];
__device__ __nv_bfloat16 g_Bl0[XW * N0];
__device__ __nv_bfloat16 g_Bh1[XW * N1];
__device__ __nv_bfloat16 g_Bl1[XW * N1];
__device__ __nv_bfloat16 g_Bh2[XW * N2];
__device__ __nv_bfloat16 g_Bl2[XW * N2];
// fp32 Y = adj @ X
__device__ float g_Y0[N0 * XW];
__device__ float g_Y1[N1 * XW];
__device__ float g_Y2[N2 * XW];

// ===========================================================================
// helpers
// ===========================================================================
__device__ __forceinline__ uint32_t smem_to_u32(const void* p) {
    uint32_t a;
    asm("{ .reg .u64 t; cvta.to.shared.u64 t, %1; cvt.u32.u64 %0, t; }" : "=r"(a) : "l"(p));
    return a;
}
__device__ __forceinline__ void ldsm4(uint32_t* r, uint32_t addr) {
    asm volatile("ldmatrix.sync.aligned.m8n8.x4.shared.b16 {%0,%1,%2,%3}, [%4];"
                 : "=r"(r[0]), "=r"(r[1]), "=r"(r[2]), "=r"(r[3]) : "r"(addr));
}
__device__ __forceinline__ void mma16816(float* c, const uint32_t* a, const uint32_t* b) {
    asm volatile(
        "mma.sync.aligned.m16n8k16.row.col.f32.bf16.bf16.f32 "
        "{%0,%1,%2,%3}, {%4,%5,%6,%7}, {%8,%9}, {%0,%1,%2,%3};"
        : "+f"(c[0]), "+f"(c[1]), "+f"(c[2]), "+f"(c[3])
        : "r"(a[0]), "r"(a[1]), "r"(a[2]), "r"(a[3]), "r"(b[0]), "r"(b[1]));
}
__device__ __forceinline__ void cpa16(uint32_t d, const void* s, int sz) {
    asm volatile("cp.async.cg.shared.global [%0], [%1], 16, %2;"
                 :: "r"(d), "l"(s), "r"(sz) : "memory");
}
#define CP_COMMIT() asm volatile("cp.async.commit_group;" ::: "memory")
#define CP_WAIT1() asm volatile("cp.async.wait_group 1;" ::: "memory")

__device__ __forceinline__ uint32_t pkbits(__nv_bfloat16 x, __nv_bfloat16 y) {
    __nv_bfloat162 t;
    t.x = x; t.y = y;
    return reinterpret_cast<uint32_t&>(t);
}
__device__ __forceinline__ void split2(float a, float b, uint32_t& hi, uint32_t& lo) {
    __nv_bfloat16 xa = __float2bfloat16_rn(a), xb = __float2bfloat16_rn(b);
    hi = pkbits(xa, xb);
    lo = pkbits(__float2bfloat16_rn(a - __bfloat162float(xa)),
                __float2bfloat16_rn(b - __bfloat162float(xb)));
}

// ===========================================================================
// Prepass: adj -> bf16 hi/lo planes (3 launches, R6-style)
// ===========================================================================
__global__ void k_cvt(const float4* __restrict__ in, uint2* __restrict__ hi,
                      uint2* __restrict__ lo, int n4) {
    int i = blockIdx.x * blockDim.x + threadIdx.x;
    int stride = gridDim.x * blockDim.x;
    for (; i < n4; i += stride) {
        float4 v = in[i];
        uint2 h, l;
        split2(v.x, v.y, h.x, l.x);
        split2(v.z, v.w, h.y, l.y);
        hi[i] = h;
        lo[i] = l;
    }
}

// ===========================================================================
// Fused zero of scatter-target B regions
// ===========================================================================
__global__ void k_zero_all(float4* __restrict__ a0, float4* __restrict__ a1,
                           float4* __restrict__ a2, float4* __restrict__ a3) {
    int i = blockIdx.x * blockDim.x + threadIdx.x;
    int st = gridDim.x * blockDim.x;
    float4 z = make_float4(0.f, 0.f, 0.f, 0.f);
    for (int k = i; k < 256000; k += st) a0[k] = z;
    for (int k = i; k < 256000; k += st) a1[k] = z;
    for (int k = i; k < 64000; k += st) a2[k] = z;
    for (int k = i; k < 64000; k += st) a3[k] = z;
}

// ===========================================================================
// Fused transposed placement: Xt[rowOff+f][r] = H[chain(r)][f] (bf16 hi/lo)
// ===========================================================================
__device__ __forceinline__ void trans_blk(float (*tile)[33],
                                          __nv_bfloat16* __restrict__ Bh,
                                          __nv_bfloat16* __restrict__ Bl, int ld,
                                          const float* __restrict__ H, int rows,
                                          const int* __restrict__ s1,
                                          const int* __restrict__ s2, int rowOff, int blk) {
    int tid = threadIdx.x;
    int r0 = blk * 32;
#pragma unroll
    for (int t = 0; t < 4; t++) {
        int g = tid + t * 256;
        int r = g >> 5;
        int c4 = g & 31;
        int sr = r0 + r;
        float4 v = make_float4(0.f, 0.f, 0.f, 0.f);
        if (sr < rows) {
            int s = sr;
            if (s2) s = s2[s];
            if (s1) s = s1[s];
            v = *reinterpret_cast<const float4*>(H + (size_t)s * DIM + c4 * 4);
        }
        tile[c4 * 4 + 0][r] = v.x;
        tile[c4 * 4 + 1][r] = v.y;
        tile[c4 * 4 + 2][r] = v.z;
        tile[c4 * 4 + 3][r] = v.w;
    }
    __syncthreads();
    int f = tid >> 1;
    int half = tid & 1;
#pragma unroll
    for (int m4 = 0; m4 < 4; m4++) {
        int lc = half * 16 + m4 * 4;
        int col = r0 + lc;
        if (col < rows) {
            uint2 h, l;
            split2(tile[f][lc], tile[f][lc + 1], h.x, l.x);
            split2(tile[f][lc + 2], tile[f][lc + 3], h.y, l.y);
            size_t off = (size_t)(rowOff + f) * ld + col;
            *reinterpret_cast<uint2*>(Bh + off) = h;
            *reinterpret_cast<uint2*>(Bl + off) = l;
        }
    }
}

__global__ __launch_bounds__(256) void k_trans_all(
    __nv_bfloat16* Bh0p, __nv_bfloat16* Bl0p, __nv_bfloat16* Bh1p, __nv_bfloat16* Bl1p,
    __nv_bfloat16* Bh2p, __nv_bfloat16* Bl2p,
    const float* h0, const float* h1, const float* h2,
    const int* idx0, const int* idx1) {
    __shared__ float tile[128][33];
    int b = blockIdx.x;
    if (b < 250)      trans_blk(tile, Bh0p, Bl0p, N0, h0, N0, nullptr, nullptr, 0, b);
    else if (b < 375) trans_blk(tile, Bh1p, Bl1p, N1, h0, N1, idx0, nullptr, 0, b - 250);
    else if (b < 500) trans_blk(tile, Bh1p, Bl1p, N1, h1, N1, nullptr, nullptr, 128, b - 375);
    else if (b < 563) trans_blk(tile, Bh2p, Bl2p, N2, h0, N2, idx0, idx1, 0, b - 500);
    else if (b < 626) trans_blk(tile, Bh2p, Bl2p, N2, h1, N2, idx1, nullptr, 128, b - 563);
    else              trans_blk(tile, Bh2p, Bl2p, N2, h2, N2, nullptr, nullptr, 256, b - 626);
}

// ===========================================================================
// Fused scattered placement (up path)
// ===========================================================================
__device__ __forceinline__ void scat_row(__nv_bfloat16* __restrict__ Bh,
                                         __nv_bfloat16* __restrict__ Bl, int ld,
                                         const float* __restrict__ H,
                                         const int* __restrict__ d1,
                                         const int* __restrict__ d2, int rowOff,
                                         int r, int f) {
    float v = H[(size_t)r * DIM + f];
    int dr = r;
    if (d2) dr = d2[dr];
    if (d1) dr = d1[dr];
    __nv_bfloat16 h = __float2bfloat16_rn(v);
    size_t off = (size_t)(rowOff + f) * ld + dr;
    Bh[off] = h;
    Bl[off] = __float2bfloat16_rn(v - __bfloat162float(h));
}

__global__ __launch_bounds__(256) void k_scatter_all(
    __nv_bfloat16* Bh0p, __nv_bfloat16* Bl0p, __nv_bfloat16* Bh1p, __nv_bfloat16* Bl1p,
    const float* h1, const float* h2, const int* idx0, const int* idx1) {
    int b = blockIdx.x;
    int f = threadIdx.x & 127;
    int rh = threadIdx.x >> 7;
    if (b < 2000)      scat_row(Bh0p, Bl0p, N0, h1, idx0, nullptr, 128, b * 2 + rh, f);
    else if (b < 3000) scat_row(Bh0p, Bl0p, N0, h2, idx0, idx1, 256, (b - 2000) * 2 + rh, f);
    else               scat_row(Bh1p, Bl1p, N1, h2, idx1, nullptr, 256, (b - 3000) * 2 + rh, f);
}

// ===========================================================================
// bf16-split mma.sync GEMM — all-ldmatrix, CTA tile M=64 x N=192.
// 3 stages x 32KB, 2 CTAs/SM. Grid: 440 CTAs (250 L0 + 126 L1 + 64 L2).
// Stage: Ah 4K | Al 4K | Bh 12K | Bl 12K = 32768 B
// ===========================================================================
#define OFF_AH 0
#define OFF_AL 4096
#define OFF_BH 8192
#define OFF_BL 20480
#define STAGE_BYTES 32768
#define SMEM_MMA (3 * STAGE_BYTES)   // 98304

__device__ __forceinline__ void issue_stage(
    uint32_t stg, const __nv_bfloat16* __restrict__ Ah, const __nv_bfloat16* __restrict__ Al,
    const __nv_bfloat16* __restrict__ Bh, const __nv_bfloat16* __restrict__ Bl,
    int rowBase, int nBase, int M, int ld, int gk0, int Klim, int tid) {
    // A hi/lo: 64 rows x 4 chunks of 16B
    {
        int row = tid >> 2, c = tid & 3;
        int gk = gk0 + c * 8;
        size_t so = (size_t)(rowBase + row) * ld + gk;
        uint32_t d = stg + row * 64 + ((c ^ ((row >> 1) & 3)) << 4);
        int p = (rowBase + row < M && gk < Klim) ? 16 : 0;
        cpa16(d + OFF_AH, Ah + so, p);
        cpa16(d + OFF_AL, Al + so, p);
    }
    // B hi/lo: 192 rows x 4 chunks of 16B
#pragma unroll
    for (int i = 0; i < 3; i++) {
        int t = tid + i * 256;
        int row = t >> 2, c = t & 3;
        int gk = gk0 + c * 8;
        size_t so = (size_t)(nBase + row) * ld + gk;
        uint32_t d = stg + row * 64 + ((c ^ ((row >> 1) & 3)) << 4);
        int p = (gk < Klim) ? 16 : 0;
        cpa16(d + OFF_BH, Bh + so, p);
        cpa16(d + OFF_BL, Bl + so, p);
    }
}

__global__ __launch_bounds__(256, 2)
void k_mma(const __nv_bfloat16* __restrict__ Ah0p, const __nv_bfloat16* __restrict__ Al0p,
           const __nv_bfloat16* __restrict__ Ah1p, const __nv_bfloat16* __restrict__ Al1p,
           const __nv_bfloat16* __restrict__ Ah2p, const __nv_bfloat16* __restrict__ Al2p,
           const __nv_bfloat16* __restrict__ Bh0p, const __nv_bfloat16* __restrict__ Bl0p,
           const __nv_bfloat16* __restrict__ Bh1p, const __nv_bfloat16* __restrict__ Bl1p,
           const __nv_bfloat16* __restrict__ Bh2p, const __nv_bfloat16* __restrict__ Bl2p,
           float* __restrict__ Y0, float* __restrict__ Y1, float* __restrict__ Y2) {
    extern __shared__ char sm[];
    int tid = threadIdx.x;
    int lane = tid & 31;
    int wid = tid >> 5;
    int bx = blockIdx.x;

    const __nv_bfloat16 *Ah, *Al, *Bh, *Bl;
    float* Y;
    int M, ld, mt, nt, nIter, Klim;
    if (bx < 250) {
        mt = bx >> 1; nt = bx & 1;
        Ah = Ah0p; Al = Al0p; Bh = Bh0p; Bl = Bl0p; Y = Y0;
        M = N0; ld = N0; nIter = 250; Klim = N0;
    } else if (bx < 376) {
        int t = bx - 250;
        mt = t >> 1; nt = t & 1;
        Ah = Ah1p; Al = Al1p; Bh = Bh1p; Bl = Bl1p; Y = Y1;
        M = N1; ld = N1; nIter = 125; Klim = N1;
    } else {
        int t = bx - 376;
        mt = t >> 1; nt = t & 1;
        Ah = Ah2p; Al = Al2p; Bh = Bh2p; Bl = Bl2p; Y = Y2;
        M = N2; ld = N2; nIter = 63; Klim = N2;
    }
    int rowBase = mt * 64;
    int nBase = nt * 192;

    uint32_t sbase = smem_to_u32(sm);
    int wm = wid & 1;    // 2 m-warps x 32 rows
    int wn = wid >> 1;   // 4 n-warps x 48 cols

    // ldmatrix geometry
    int rA = lane & 15;
    int cA = lane >> 4;
    int rBl = (lane & 7) + ((lane >> 4) & 1) * 8;
    int cB = (lane >> 3) & 1;
    uint32_t arow[2], aswz[2], brow[3], bswz[3];
#pragma unroll
    for (int mi = 0; mi < 2; mi++) {
        int r = wm * 32 + mi * 16 + rA;
        arow[mi] = (uint32_t)r * 64;
        aswz[mi] = (r >> 1) & 3;
    }
#pragma unroll
    for (int nb = 0; nb < 3; nb++) {
        int r = wn * 48 + nb * 16 + rBl;
        brow[nb] = (uint32_t)r * 64;
        bswz[nb] = (r >> 1) & 3;
    }

    float acc[2][6][4];
#pragma unroll
    for (int mi = 0; mi < 2; mi++)
#pragma unroll
        for (int ni = 0; ni < 6; ni++)
#pragma unroll
            for (int c = 0; c < 4; c++) acc[mi][ni][c] = 0.f;

    // prologue: 2 stages
#pragma unroll
    for (int s = 0; s < 2; s++) {
        issue_stage(sbase + s * STAGE_BYTES, Ah, Al, Bh, Bl, rowBase, nBase, M, ld,
                    s * 32, Klim, tid);
        CP_COMMIT();
    }

    int st = 0;  // stage index of current iter (mod 3)
    for (int it = 0; it < nIter; it++) {
        CP_WAIT1();
        __syncthreads();
        {
            int nst = st + 2; if (nst >= 3) nst -= 3;
            if (it + 2 < nIter)
                issue_stage(sbase + nst * STAGE_BYTES, Ah, Al, Bh, Bl, rowBase, nBase,
                            M, ld, (it + 2) * 32, Klim, tid);
            CP_COMMIT();
        }

        uint32_t stg = sbase + st * STAGE_BYTES;
#pragma unroll
        for (int k16 = 0; k16 < 2; k16++) {
            uint32_t ah[2][4], al[2][4], bh[3][4], bl[3][4];
#pragma unroll
            for (int mi = 0; mi < 2; mi++) {
                uint32_t off = arow[mi] + ((((uint32_t)(k16 * 2 + cA)) ^ aswz[mi]) << 4);
                ldsm4(ah[mi], stg + OFF_AH + off);
                ldsm4(al[mi], stg + OFF_AL + off);
            }
#pragma unroll
            for (int nb = 0; nb < 3; nb++) {
                uint32_t off = brow[nb] + ((((uint32_t)(k16 * 2 + cB)) ^ bswz[nb]) << 4);
                ldsm4(bh[nb], stg + OFF_BH + off);
                ldsm4(bl[nb], stg + OFF_BL + off);
            }
#pragma unroll
            for (int mi = 0; mi < 2; mi++)
#pragma unroll
                for (int nb = 0; nb < 3; nb++) {
                    mma16816(acc[mi][2 * nb], ah[mi], &bh[nb][0]);
                    mma16816(acc[mi][2 * nb + 1], ah[mi], &bh[nb][2]);
                    mma16816(acc[mi][2 * nb], al[mi], &bh[nb][0]);
                    mma16816(acc[mi][2 * nb + 1], al[mi], &bh[nb][2]);
                    mma16816(acc[mi][2 * nb], ah[mi], &bl[nb][0]);
                    mma16816(acc[mi][2 * nb + 1], ah[mi], &bl[nb][2]);
                }
        }
        if (++st == 3) st = 0;
    }

    int colB = nBase + wn * 48 + (lane & 3) * 2;
#pragma unroll
    for (int mi = 0; mi < 2; mi++)
#pragma unroll
        for (int h = 0; h < 2; h++) {
            int row = rowBase + wm * 32 + mi * 16 + (lane >> 2) + h * 8;
            if (row < M) {
                float* yp = Y + (size_t)row * XW + colB;
#pragma unroll
                for (int ni = 0; ni < 6; ni++)
                    *reinterpret_cast<float2*>(yp + ni * 8) =
                        make_float2(acc[mi][ni][2 * h], acc[mi][ni][2 * h + 1]);
            }
        }
}

// ===========================================================================
// Fused fp32 epilogue: out_i = sum_j relu(Y_i[:,jblk] @ W[i,j] + b[i,j])
// ===========================================================================
__global__ __launch_bounds__(256) void k_epi(const float* __restrict__ Y0a,
                                             const float* __restrict__ Y1a,
                                             const float* __restrict__ Y2a,
                                             const float* __restrict__ Wall,
                                             const float* __restrict__ ball,
                                             float* __restrict__ outAll) {
    __shared__ float As[16][132];
    __shared__ float Bs[16][128];
    int tid = threadIdx.x;
    int tx = tid & 15;
    int ty = tid >> 4;
    int bx = blockIdx.x;

    const float* Y;
    float* out;
    int M, ilev, mt;
    if (bx < 63) {
        Y = Y0a; out = outAll; M = N0; ilev = 0; mt = bx;
    } else if (bx < 95) {
        Y = Y1a; out = outAll + (size_t)N0 * DIM; M = N1; ilev = 1; mt = bx - 63;
    } else {
        Y = Y2a; out = outAll + (size_t)(N0 + N1) * DIM; M = N2; ilev = 2; mt = bx - 95;
    }
    int rowBase = mt * 128;

    float sum[8][8];
#pragma unroll
    for (int i = 0; i < 8; i++)
#pragma unroll
        for (int j = 0; j < 8; j++) sum[i][j] = 0.f;

    for (int jb = 0; jb < 3; jb++) {
        const float* W = Wall + (size_t)(ilev * 3 + jb) * DIM * DIM;
        float acc[8][8];
#pragma unroll
        for (int i = 0; i < 8; i++)
#pragma unroll
            for (int j = 0; j < 8; j++) acc[i][j] = 0.f;

        for (int k0 = 0; k0 < DIM; k0 += 16) {
#pragma unroll
            for (int l = 0; l < 2; l++) {
                int s = tid + l * 256;
                int r = s >> 2;
                int kq = (s & 3) * 4;
                int grow = rowBase + r;
                float4 v = make_float4(0.f, 0.f, 0.f, 0.f);
                if (grow < M)
                    v = *reinterpret_cast<const float4*>(Y + (size_t)grow * XW + jb * DIM + k0 + kq);
                As[kq + 0][r] = v.x;
                As[kq + 1][r] = v.y;
                As[kq + 2][r] = v.z;
                As[kq + 3][r] = v.w;
            }
#pragma unroll
            for (int l = 0; l < 2; l++) {
                int s = tid + l * 256;
                int kr = s >> 5;
                int c4 = (s & 31) * 4;
                *reinterpret_cast<float4*>(&Bs[kr][c4]) =
                    *reinterpret_cast<const float4*>(W + (size_t)(k0 + kr) * DIM + c4);
            }
            __syncthreads();
#pragma unroll
            for (int kk = 0; kk < 16; kk++) {
                float a[8], b[8];
                *reinterpret_cast<float4*>(a) = *reinterpret_cast<const float4*>(&As[kk][ty * 8]);
                *reinterpret_cast<float4*>(a + 4) = *reinterpret_cast<const float4*>(&As[kk][ty * 8 + 4]);
                *reinterpret_cast<float4*>(b) = *reinterpret_cast<const float4*>(&Bs[kk][tx * 8]);
                *reinterpret_cast<float4*>(b + 4) = *reinterpret_cast<const float4*>(&Bs[kk][tx * 8 + 4]);
#pragma unroll
                for (int i = 0; i < 8; i++)
#pragma unroll
                    for (int j = 0; j < 8; j++) acc[i][j] += a[i] * b[j];
            }
            __syncthreads();
        }
        const float* bvec = ball + (size_t)(ilev * 3 + jb) * DIM;
#pragma unroll
        for (int j = 0; j < 8; j++) {
            float bb = bvec[tx * 8 + j];
#pragma unroll
            for (int i = 0; i < 8; i++) sum[i][j] += fmaxf(acc[i][j] + bb, 0.f);
        }
    }

#pragma unroll
    for (int i = 0; i < 8; i++) {
        int grow = rowBase + ty * 8 + i;
        if (grow < M) {
            float* op = out + (size_t)grow * DIM + tx * 8;
            *reinterpret_cast<float4*>(op) = make_float4(sum[i][0], sum[i][1], sum[i][2], sum[i][3]);
            *reinterpret_cast<float4*>(op + 4) = make_float4(sum[i][4], sum[i][5], sum[i][6], sum[i][7]);
        }
    }
}

// ===========================================================================
extern "C" void kernel_launch(void* const* d_in, const int* in_sizes, int n_in,
                              void* d_out, int out_size) {
    const float* adj0 = (const float*)d_in[0];
    const float* adj1 = (const float*)d_in[1];
    const float* adj2 = (const float*)d_in[2];
    const float* h0 = (const float*)d_in[3];
    const float* h1 = (const float*)d_in[4];
    const float* h2 = (const float*)d_in[5];
    const int* idx0 = (const int*)d_in[6];
    const int* idx1 = (const int*)d_in[7];
    const float* Ws = (const float*)d_in[8];
    const float* bs = (const float*)d_in[9];
    float* out = (float*)d_out;

    __nv_bfloat16 *Ah0, *Al0, *Ah1, *Al1, *Ah2, *Al2;
    __nv_bfloat16 *Bh0, *Bl0, *Bh1, *Bl1, *Bh2, *Bl2;
    float *Y0, *Y1, *Y2;
    cudaGetSymbolAddress((void**)&Ah0, g_Ah0);
    cudaGetSymbolAddress((void**)&Al0, g_Al0);
    cudaGetSymbolAddress((void**)&Ah1, g_Ah1);
    cudaGetSymbolAddress((void**)&Al1, g_Al1);
    cudaGetSymbolAddress((void**)&Ah2, g_Ah2);
    cudaGetSymbolAddress((void**)&Al2, g_Al2);
    cudaGetSymbolAddress((void**)&Bh0, g_Bh0);
    cudaGetSymbolAddress((void**)&Bl0, g_Bl0);
    cudaGetSymbolAddress((void**)&Bh1, g_Bh1);
    cudaGetSymbolAddress((void**)&Bl1, g_Bl1);
    cudaGetSymbolAddress((void**)&Bh2, g_Bh2);
    cudaGetSymbolAddress((void**)&Bl2, g_Bl2);
    cudaGetSymbolAddress((void**)&Y0, g_Y0);
    cudaGetSymbolAddress((void**)&Y1, g_Y1);
    cudaGetSymbolAddress((void**)&Y2, g_Y2);

    cudaFuncSetAttribute(k_mma, cudaFuncAttributeMaxDynamicSharedMemorySize, SMEM_MMA);

    // 1. adj -> bf16 hi/lo (3 launches, R6-style)
    k_cvt<<<2048, 256>>>((const float4*)adj0, (uint2*)Ah0, (uint2*)Al0, (int)((size_t)N0 * N0 / 4));
    k_cvt<<<1024, 256>>>((const float4*)adj1, (uint2*)Ah1, (uint2*)Al1, N1 * N1 / 4);
    k_cvt<<<512, 256>>>((const float4*)adj2, (uint2*)Ah2, (uint2*)Al2, N2 * N2 / 4);

    // 2. Zero scatter-target B regions
    k_zero_all<<<640, 256>>>((float4*)(Bh0 + (size_t)128 * N0),
                             (float4*)(Bl0 + (size_t)128 * N0),
                             (float4*)(Bh1 + (size_t)256 * N1),
                             (float4*)(Bl1 + (size_t)256 * N1));

    // 3. Build Xt bf16 hi/lo
    k_trans_all<<<689, 256>>>(Bh0, Bl0, Bh1, Bl1, Bh2, Bl2, h0, h1, h2, idx0, idx1);
    k_scatter_all<<<4000, 256>>>(Bh0, Bl0, Bh1, Bl1, h1, h2, idx0, idx1);

    // 4. Y_i = adj_i @ X_i — N=192 tiles, 3-stage cp.async, all-ldmatrix
    k_mma<<<440, 256, SMEM_MMA>>>(Ah0, Al0, Ah1, Al1, Ah2, Al2,
                                  Bh0, Bl0, Bh1, Bl1, Bh2, Bl2, Y0, Y1, Y2);

    // 5. Fused epilogue
    k_epi<<<111, 256>>>(Y0, Y1, Y2, Ws, bs, out);
}